// round 9
// baseline (speedup 1.0000x reference)
#include <cuda_runtime.h>

// DDK_77644418777653 — per-row recurrence scan, transposed-tile SMEM staging.
//
// out[:,0] = 1 ; out[:,k] = out[:,k-1] + alpha/out[:,k-1] - beta*in[:,k-1]
// M = 262144 rows, N = 512 cols, fp32, row-major.
//
// R6 structure (200.8us, rel_err=0.0) + three additive changes:
//   * __launch_bounds__(256, 5): cap regs at 51 -> 5 CTAs/SM (40 warps),
//     better cross-CTA phase staggering so DRAM stays busy during the
//     serial-divide phases.
//   * __ldcs / __stcs: input is read-once, output write-once -> evict-first
//     L2 policy, no pollution from the 1 GB single-use stream.
//   * load phase explicitly front-batches all 8 LDG.128 before the STS
//     burst (MLP=8 per thread, no interleaved dependence).
//
// Bank maps (verified conflict-free, TK=32 only — TK=16 is provably
// incompatible with odd compute stride, see R8 post-mortem):
//   staging: warp = 4 rows x 8 slots, bank = (r + 4c) mod 32 -> all 32 banks
//   compute: stride 33 (odd) -> 32 distinct banks
//
// fp semantics are bit-exact vs XLA:GPU's lowering (rel_err=0.0 in R6 —
// do NOT change):
//   t  = div.rn(a, w)
//   u  = add.rn(w, t)
//   w' = ffma.rn(-b, x, u)

#define ROWS_PER_BLOCK 256
#define TK             32
#define LDSR           33   // padded smem row stride (odd -> conflict-free)
#define NCOLS          512
#define N4             (NCOLS / 4)
#define LD_IT          ((ROWS_PER_BLOCK * TK / 4) / ROWS_PER_BLOCK)  // 8

__global__ __launch_bounds__(ROWS_PER_BLOCK, 5)
void DDK_77644418777653_kernel(const float* __restrict__ in,
                               const float* __restrict__ alpha,
                               const float* __restrict__ beta,
                               float* __restrict__ out) {
    __shared__ float sm[ROWS_PER_BLOCK * LDSR];   // 33792 B

    const int tid  = threadIdx.x;
    const int row0 = blockIdx.x * ROWS_PER_BLOCK;

    const float a = alpha[0];
    const float b = beta[0];

    const float4* in4  = reinterpret_cast<const float4*>(in);
    float4*       out4 = reinterpret_cast<float4*>(out);

    // Staging slots this thread services: idx = it*256 + tid,
    // r = idx>>3 (4 consecutive rows per warp), c4 = idx&7.
    int rr[LD_IT], cc[LD_IT];
    #pragma unroll
    for (int it = 0; it < LD_IT; ++it) {
        int idx = it * ROWS_PER_BLOCK + tid;
        rr[it] = idx >> 3;
        cc[it] = idx & 7;
    }

    float w     = 1.0f;   // recurrence state for this thread's row
    float xprev = 0.0f;   // input value carried across tile boundary
    bool  first = true;   // col 0 of the whole row is exactly 1

    for (int t = 0; t < NCOLS / TK; ++t) {
        const int kc4 = t * (TK / 4);

        // ---- coalesced load: 8 streaming LDG.128 front-batched, then STS ----
        {
            float4 pf[LD_IT];
            #pragma unroll
            for (int it = 0; it < LD_IT; ++it)
                pf[it] = __ldcs(&in4[(size_t)(row0 + rr[it]) * N4 + kc4 + cc[it]]);
            #pragma unroll
            for (int it = 0; it < LD_IT; ++it) {
                float* d = &sm[rr[it] * LDSR + cc[it] * 4];
                d[0] = pf[it].x; d[1] = pf[it].y;
                d[2] = pf[it].z; d[3] = pf[it].w;
            }
        }
        __syncthreads();

        // ---- per-thread serial recurrence over this tile (in-place) ----
        float* mrow = &sm[tid * LDSR];
        #pragma unroll
        for (int i = 0; i < TK; ++i) {
            float x = mrow[i];  // input col t*TK+i (read before overwrite)
            // out col uses input col-1 = xprev. Exact XLA op sequence.
            float u  = __fadd_rn(w, __fdiv_rn(a, w));
            float wn = __fmaf_rn(-b, xprev, u);
            w = first ? 1.0f : wn;
            mrow[i] = w;
            xprev   = x;
            first   = false;     // constant-folds away for i >= 1
        }
        __syncthreads();

        // ---- coalesced streaming store of the tile ----
        #pragma unroll
        for (int it = 0; it < LD_IT; ++it) {
            const float* s = &sm[rr[it] * LDSR + cc[it] * 4];
            __stcs(&out4[(size_t)(row0 + rr[it]) * N4 + kc4 + cc[it]],
                   make_float4(s[0], s[1], s[2], s[3]));
        }
        __syncthreads();   // smem reads done before next tile's STS overwrite
    }
}

extern "C" void kernel_launch(void* const* d_in, const int* in_sizes, int n_in,
                              void* d_out, int out_size) {
    const float* in    = (const float*)d_in[0];   // [262144, 512] fp32
    const float* alpha = (const float*)d_in[1];   // [1]
    const float* beta  = (const float*)d_in[2];   // [1]
    float*       out   = (float*)d_out;           // [262144, 512] fp32

    const int M = in_sizes[0] / NCOLS;            // 262144
    DDK_77644418777653_kernel<<<M / ROWS_PER_BLOCK, ROWS_PER_BLOCK>>>(
        in, alpha, beta, out);
}